// round 14
// baseline (speedup 1.0000x reference)
#include <cuda_runtime.h>
#include <math.h>
#include <float.h>

#define F_FRAMES 128
#define NPRED    300
#define MTGT     32
#define NCLS     2
#define KID      512

#define HTHREADS 320
#define NWARPS   (HTHREADS/32)
#define KPL      10   // columns per lane in solver warp

__device__ double   g_part[F_FRAMES * 3];  // per-frame [l1_sum, giou_sum, nll_sum]
__device__ unsigned g_done = 0;            // self-resetting completion counter

struct XY { float x1, y1, x2, y2, area; };

__device__ __forceinline__ XY to_xyxy(float cx, float cy, float w, float h) {
    XY r;
    r.x1 = cx - 0.5f * w; r.y1 = cy - 0.5f * h;
    r.x2 = cx + 0.5f * w; r.y2 = cy + 0.5f * h;
    r.area = (r.x2 - r.x1) * (r.y2 - r.y1);
    return r;
}

__device__ __forceinline__ float giou_xy(const XY& a, const XY& b) {
    float ltx = fmaxf(a.x1, b.x1), lty = fmaxf(a.y1, b.y1);
    float rbx = fminf(a.x2, b.x2), rby = fminf(a.y2, b.y2);
    float w = fmaxf(rbx - ltx, 0.f), h = fmaxf(rby - lty, 0.f);
    float inter = w * h;
    float uni = a.area + b.area - inter;
    float iou = inter / uni;
    float LTx = fminf(a.x1, b.x1), LTy = fminf(a.y1, b.y1);
    float RBx = fmaxf(a.x2, b.x2), RBy = fmaxf(a.y2, b.y2);
    float W = fmaxf(RBx - LTx, 0.f), H = fmaxf(RBy - LTy, 0.f);
    float ac = W * H;
    return iou - (ac - uni) / ac;
}

// order-preserving float -> u32 (smaller float => smaller key)
__device__ __forceinline__ unsigned f2key(float f) {
    unsigned b = __float_as_uint(f);
    return (b & 0x80000000u) ? ~b : (b | 0x80000000u);
}
__device__ __forceinline__ float key2f(unsigned k) {
    unsigned b = (k & 0x80000000u) ? (k ^ 0x80000000u) : ~k;
    return __uint_as_float(b);
}

__global__ __launch_bounds__(HTHREADS, 1)
void motip_kernel(const float* __restrict__ pl,   // [F,N,2]
                  const float* __restrict__ pb,   // [F,N,4]
                  const float* __restrict__ il,   // [F,N,512]
                  const int*   __restrict__ tlab, // [F,M]
                  const float* __restrict__ tbx,  // [F,M,4]
                  const int*   __restrict__ tids, // [F,M]
                  float* __restrict__ out)        // [5]
{
    const int f    = blockIdx.x;
    const int tid  = threadIdx.x;
    const int lane = tid & 31;
    const int wid  = tid >> 5;

    __shared__ float  s_cost[MTGT * NPRED];   // [t][j]
    __shared__ float  s_u[MTGT + 1];
    __shared__ int    s_way[NPRED + 1];
    __shared__ int    s_p[NPRED + 1];
    __shared__ XY     s_tb[MTGT];
    __shared__ int    s_tl[MTGT];
    __shared__ unsigned long long s_rowkey[MTGT];
    __shared__ int    s_freelist[MTGT];
    __shared__ int    s_nfree;
    __shared__ int    s_match[MTGT];
    __shared__ double s_acc[3];
    __shared__ int    s_islast;

    // ---- init + load targets ----
    if (tid < MTGT) {
        const float* t = tbx + (size_t)(f * MTGT + tid) * 4;
        s_tb[tid] = to_xyxy(t[0], t[1], t[2], t[3]);
        s_tl[tid] = tlab[f * MTGT + tid];
    }
    if (tid <= NPRED) s_p[tid] = 0;
    if (tid < 3)      s_acc[tid] = 0.0;
    __syncthreads();

    // ---- cost build: thread j handles pred j ----
    if (tid < NPRED) {
        const float* lg = pl + (size_t)(f * NPRED + tid) * NCLS;
        float x0 = lg[0], x1 = lg[1];
        float mx = fmaxf(x0, x1);
        float e0 = expf(x0 - mx), e1 = expf(x1 - mx);
        float inv = 1.0f / (e0 + e1);
        float prob[2] = { e0 * inv, e1 * inv };

        const float* bp = pb + (size_t)(f * NPRED + tid) * 4;
        float cx = bp[0], cy = bp[1], bw = bp[2], bh = bp[3];
        XY a = to_xyxy(cx, cy, bw, bh);

        #pragma unroll 4
        for (int t = 0; t < MTGT; t++) {
            const float* tb4 = tbx + (size_t)(f * MTGT + t) * 4;
            float l1 = fabsf(cx - tb4[0]) + fabsf(cy - tb4[1])
                     + fabsf(bw - tb4[2]) + fabsf(bh - tb4[3]);
            float g  = giou_xy(a, s_tb[t]);
            float cc = -prob[s_tl[t]];
            s_cost[t * NPRED + tid] = 2.0f * cc + 5.0f * l1 + 2.0f * (-g);
        }
    }
    __syncthreads();

    // ---- row minima: warp w handles rows w, w+10, ... ----
    for (int r = wid; r < MTGT; r += NWARPS) {
        unsigned long long best = 0xFFFFFFFFFFFFFFFFULL;
        #pragma unroll
        for (int k = 0; k < KPL; k++) {
            int j = lane + 32 * k;
            if (j < NPRED) {
                unsigned long long key =
                    ((unsigned long long)f2key(s_cost[r * NPRED + j]) << 32)
                    | (unsigned)j;
                best = min(best, key);
            }
        }
        #pragma unroll
        for (int off = 16; off > 0; off >>= 1)
            best = min(best, __shfl_xor_sync(0xffffffffu, best, off));
        if (lane == 0) s_rowkey[r] = best;
    }
    __syncthreads();

    // ---- greedy tight assignment + dual init (tid 0, serial over 32 rows) ----
    if (tid == 0) {
        int nf = 0;
        s_u[0] = 0.0f;
        for (int r = 0; r < MTGT; r++) {
            unsigned long long key = s_rowkey[r];
            int   jmin = (int)(key & 0xFFFFFFFFULL);
            float vmin = key2f((unsigned)(key >> 32));
            s_u[r + 1] = vmin;                    // u[i] = exact row min, v = 0
            if (s_p[jmin + 1] == 0) s_p[jmin + 1] = r + 1;   // tight edge, free col
            else                    s_freelist[nf++] = r + 1;
        }
        s_nfree = nf;
    }
    __syncthreads();

    // ---- JV augmentation: warp 0 only, fully warp-synchronous.
    //      Lane owns columns j = lane + 32k + 1 (k=0..9); v/mv/rof in registers.
    if (wid == 0) {
        float v[KPL];
        #pragma unroll
        for (int k = 0; k < KPL; k++) v[k] = 0.0f;   // greedy init leaves v = 0

        const int nfree = s_nfree;
        for (int fi = 0; fi < nfree; fi++) {
            const int irow = s_freelist[fi];
            float mv[KPL];
            int   rof[KPL];
            #pragma unroll
            for (int k = 0; k < KPL; k++) { mv[k] = FLT_MAX; rof[k] = 0; }
            unsigned usedm = 0;
            int i0 = irow;
            int j0 = 0;
            int j1 = 0, pj1 = 0;
            if (lane == 0) s_p[0] = irow;   // for augment chain terminal

            while (true) {
                const float u_i0 = s_u[i0];   // row untouched so far in this path

                // compute + lane-local argmin (lowest j on ties via ascending k, strict <)
                float bestv = FLT_MAX;
                int   bestj = 0x7fffffff;
                #pragma unroll
                for (int k = 0; k < KPL; k++) {
                    const int  j     = lane + 32 * k + 1;
                    const bool valid = (k < KPL - 1) || (lane < NPRED - 32 * (KPL - 1));
                    if (valid && !((usedm >> k) & 1u)) {
                        float cur = s_cost[(i0 - 1) * NPRED + (j - 1)] - u_i0 - v[k];
                        if (cur < mv[k]) { mv[k] = cur; s_way[j] = j0; }
                        if (mv[k] < bestv) { bestv = mv[k]; bestj = j; }
                    }
                }

                // warp argmin: REDUX value, then lowest-index tie-break
                unsigned vkey = f2key(bestv);
                unsigned vmin = __reduce_min_sync(0xffffffffu, vkey);
                unsigned jc   = (vkey == vmin) ? (unsigned)bestj : 0xFFFFFFFFu;
                j1 = (int)__reduce_min_sync(0xffffffffu, jc);
                const float delta = key2f(vmin);   // == owner's mv, exact
                pj1 = s_p[j1];                     // stable during path

                // update (pre-selection used set, matching reference semantics)
                if (lane == 0) s_u[irow] += delta;
                #pragma unroll
                for (int k = 0; k < KPL; k++) {
                    const int  j     = lane + 32 * k + 1;
                    const bool valid = (k < KPL - 1) || (lane < NPRED - 32 * (KPL - 1));
                    if (valid) {
                        if ((usedm >> k) & 1u) {
                            v[k] -= delta;
                            s_u[rof[k]] += delta;   // distinct rows, no conflict
                        } else {
                            mv[k] -= delta;
                            if (j == j1) {          // becomes used for next iter
                                usedm |= 1u << k;
                                rof[k] = pj1;
                            }
                        }
                    }
                }

                i0 = pj1;
                j0 = j1;
                if (pj1 == 0) break;
            }

            // augment (scalar chain over s_way)
            __syncwarp();       // s_way stores visible to lane 0
            if (lane == 0) {
                int jj = j0;
                while (jj) {
                    int jn = s_way[jj];
                    s_p[jj] = s_p[jn];
                    jj = jn;
                }
            }
            __syncwarp();       // s_p visible to all lanes for next path
        }
    }
    __syncthreads();

    // ---- emit matches to smem ----
    if (tid < NPRED) {
        const int r = s_p[tid + 1];
        if (r > 0) s_match[r - 1] = tid;
    }
    __syncthreads();

    // ---- L1 + pair GIoU: one thread per target ----
    if (tid < MTGT) {
        const int idx = s_match[tid];
        const float* bp2 = pb  + (size_t)(f * NPRED + idx) * 4;
        const float* bt  = tbx + (size_t)(f * MTGT + tid) * 4;
        float l1 = fabsf(bp2[0] - bt[0]) + fabsf(bp2[1] - bt[1])
                 + fabsf(bp2[2] - bt[2]) + fabsf(bp2[3] - bt[3]);
        XY a = to_xyxy(bp2[0], bp2[1], bp2[2], bp2[3]);
        XY b = to_xyxy(bt[0], bt[1], bt[2], bt[3]);
        float g = giou_xy(a, b);
        atomicAdd(&s_acc[0], (double)l1);
        atomicAdd(&s_acc[1], (double)g);
    }

    // ---- ID cross-entropy: each warp handles ~3-4 rows of K=512 ----
    double id_part = 0.0;
    for (int t = wid; t < MTGT; t += NWARPS) {
        const int idx = s_match[t];
        const float* row = il + (size_t)(f * NPRED + idx) * KID;
        float xv[16];
        float mx = -FLT_MAX;
        #pragma unroll
        for (int k = 0; k < 16; k++) {
            xv[k] = row[lane + 32 * k];
            mx = fmaxf(mx, xv[k]);
        }
        #pragma unroll
        for (int off = 16; off > 0; off >>= 1)
            mx = fmaxf(mx, __shfl_xor_sync(0xffffffffu, mx, off));
        float se = 0.f;
        #pragma unroll
        for (int k = 0; k < 16; k++) se += __expf(xv[k] - mx);
        #pragma unroll
        for (int off = 16; off > 0; off >>= 1)
            se += __shfl_xor_sync(0xffffffffu, se, off);
        if (lane == 0) {
            float lse = logf(se) + mx;
            int tg = tids[f * MTGT + t];
            id_part += (double)(lse - row[tg]);
        }
    }
    if (lane == 0 && id_part != 0.0) atomicAdd(&s_acc[2], id_part);
    __syncthreads();

    // ---- publish partials; last block finalizes ----
    if (tid == 0) {
        g_part[f * 3 + 0] = s_acc[0];
        g_part[f * 3 + 1] = s_acc[1];
        g_part[f * 3 + 2] = s_acc[2];
        __threadfence();
        unsigned t = atomicAdd(&g_done, 1u);
        s_islast = (t == F_FRAMES - 1) ? 1 : 0;
    }
    __syncthreads();

    if (s_islast) {
        __threadfence();
        double a0 = 0.0, a1 = 0.0, a2 = 0.0;
        if (tid < F_FRAMES) {
            a0 = g_part[tid * 3 + 0];
            a1 = g_part[tid * 3 + 1];
            a2 = g_part[tid * 3 + 2];
        }
        #pragma unroll
        for (int off = 16; off > 0; off >>= 1) {
            a0 += __shfl_down_sync(0xffffffffu, a0, off);
            a1 += __shfl_down_sync(0xffffffffu, a1, off);
            a2 += __shfl_down_sync(0xffffffffu, a2, off);
        }
        __shared__ double s0[4], s1[4], s2[4];
        if (lane == 0 && wid < 4) { s0[wid] = a0; s1[wid] = a1; s2[wid] = a2; }
        __syncthreads();
        if (tid == 0) {
            double t0 = s0[0] + s0[1] + s0[2] + s0[3];
            double t1 = s1[0] + s1[1] + s1[2] + s1[3];
            double t2 = s2[0] + s2[1] + s2[2] + s2[3];
            const double FM = (double)(F_FRAMES * MTGT);
            double l1   = t0 / (FM * 4.0);
            double giou = 1.0 - t1 / FM;
            double idl  = t2 / FM;
            double loss = 5.0 * l1 + 2.0 * giou + 1.0 * idl;
            out[0] = (float)loss;
            out[1] = 0.0f;
            out[2] = (float)l1;
            out[3] = (float)giou;
            out[4] = (float)idl;
            __threadfence();
            g_done = 0;      // self-reset for next graph replay
        }
    }
}

extern "C" void kernel_launch(void* const* d_in, const int* in_sizes, int n_in,
                              void* d_out, int out_size) {
    const float* pred_logits   = (const float*)d_in[0];  // [8,16,300,2]
    const float* pred_boxes    = (const float*)d_in[1];  // [8,16,300,4]
    const float* id_logits     = (const float*)d_in[2];  // [8,16,300,512]
    const int*   target_labels = (const int*)  d_in[3];  // [128,32]
    const float* target_boxes  = (const float*)d_in[4];  // [128,32,4]
    const int*   target_ids    = (const int*)  d_in[5];  // [128,32]
    float* out = (float*)d_out;

    motip_kernel<<<F_FRAMES, HTHREADS>>>(pred_logits, pred_boxes, id_logits,
                                         target_labels, target_boxes, target_ids,
                                         out);
}

// round 15
// speedup vs baseline: 1.4989x; 1.4989x over previous
#include <cuda_runtime.h>
#include <math.h>
#include <float.h>

#define F_FRAMES 128
#define NPRED    300
#define MTGT     32
#define NCLS     2
#define KID      512

#define HTHREADS 320
#define NWARPS   (HTHREADS/32)

__device__ double   g_part[F_FRAMES * 3];  // per-frame [l1_sum, giou_sum, nll_sum]
__device__ unsigned g_done = 0;            // self-resetting completion counter

// order-preserving float -> u32 (smaller float => smaller key)
__device__ __forceinline__ unsigned f2key(float f) {
    unsigned b = __float_as_uint(f);
    return (b & 0x80000000u) ? ~b : (b | 0x80000000u);
}
__device__ __forceinline__ float key2f(unsigned k) {
    unsigned b = (k & 0x80000000u) ? (k ^ 0x80000000u) : ~k;
    return __uint_as_float(b);
}

__global__ __launch_bounds__(HTHREADS, 1)
void motip_kernel(const float* __restrict__ pl,   // [F,N,2]
                  const float* __restrict__ pb,   // [F,N,4]
                  const float* __restrict__ il,   // [F,N,512]
                  const int*   __restrict__ tlab, // [F,M]
                  const float* __restrict__ tbx,  // [F,M,4]
                  const int*   __restrict__ tids, // [F,M]
                  float* __restrict__ out)        // [5]
{
    const int f    = blockIdx.x;
    const int tid  = threadIdx.x;
    const int lane = tid & 31;
    const int wid  = tid >> 5;

    __shared__ float  s_cost[MTGT * NPRED];   // [t][j]
    __shared__ float  s_u[MTGT + 1];
    __shared__ int    s_way[NPRED + 1];
    __shared__ int    s_p[NPRED + 1];
    __shared__ float4 s_tc[MTGT];             // target cxcywh
    __shared__ float4 s_tb4[MTGT];            // target xyxy
    __shared__ float  s_ta[MTGT];             // target area
    __shared__ int    s_tl[MTGT];
    __shared__ unsigned long long s_wmin[2][NWARPS];  // parity double-buffer
    __shared__ unsigned long long s_rowkey[MTGT];
    __shared__ int    s_freelist[MTGT];
    __shared__ int    s_nfree;
    __shared__ int    s_match[MTGT];
    __shared__ double s_acc[3];
    __shared__ int    s_islast;

    // ---- init + load targets (vector loads) ----
    if (tid < MTGT) {
        const float4 t = ((const float4*)tbx)[f * MTGT + tid];
        s_tc[tid] = t;
        float x1 = t.x - 0.5f * t.z, y1 = t.y - 0.5f * t.w;
        float x2 = t.x + 0.5f * t.z, y2 = t.y + 0.5f * t.w;
        s_tb4[tid] = make_float4(x1, y1, x2, y2);
        s_ta[tid]  = (x2 - x1) * (y2 - y1);
        s_tl[tid]  = tlab[f * MTGT + tid];
    }
    if (tid <= NPRED) s_p[tid] = 0;
    if (tid < 3)      s_acc[tid] = 0.0;
    __syncthreads();

    // ---- cost build: thread j handles pred j ----
    if (tid < NPRED) {
        const float2 lg = ((const float2*)pl)[f * NPRED + tid];
        float mx = fmaxf(lg.x, lg.y);
        float e0 = expf(lg.x - mx), e1 = expf(lg.y - mx);
        float inv = 1.0f / (e0 + e1);
        float prob[2] = { e0 * inv, e1 * inv };

        const float4 bp = ((const float4*)pb)[f * NPRED + tid];
        const float ax1 = bp.x - 0.5f * bp.z, ay1 = bp.y - 0.5f * bp.w;
        const float ax2 = bp.x + 0.5f * bp.z, ay2 = bp.y + 0.5f * bp.w;
        const float aarea = (ax2 - ax1) * (ay2 - ay1);

        #pragma unroll 4
        for (int t = 0; t < MTGT; t++) {
            const float4 tc = s_tc[t];
            const float4 tb = s_tb4[t];
            const float  ta = s_ta[t];
            float l1 = fabsf(bp.x - tc.x) + fabsf(bp.y - tc.y)
                     + fabsf(bp.z - tc.z) + fabsf(bp.w - tc.w);
            // inline giou with fast divides
            float ltx = fmaxf(ax1, tb.x), lty = fmaxf(ay1, tb.y);
            float rbx = fminf(ax2, tb.z), rby = fminf(ay2, tb.w);
            float iw = fmaxf(rbx - ltx, 0.f), ih = fmaxf(rby - lty, 0.f);
            float inter = iw * ih;
            float uni = aarea + ta - inter;
            float iou = __fdividef(inter, uni);
            float LTx = fminf(ax1, tb.x), LTy = fminf(ay1, tb.y);
            float RBx = fmaxf(ax2, tb.z), RBy = fmaxf(ay2, tb.w);
            float ac = fmaxf(RBx - LTx, 0.f) * fmaxf(RBy - LTy, 0.f);
            float g = iou - __fdividef(ac - uni, ac);
            float cc = -prob[s_tl[t]];
            s_cost[t * NPRED + tid] = 2.0f * cc + 5.0f * l1 - 2.0f * g;
        }
    }
    __syncthreads();

    // ---- row minima: warp w handles rows w, w+10, ... ----
    for (int r = wid; r < MTGT; r += NWARPS) {
        unsigned long long best = 0xFFFFFFFFFFFFFFFFULL;
        #pragma unroll
        for (int k = 0; k < 10; k++) {
            int j = lane + 32 * k;
            if (j < NPRED) {
                unsigned long long key =
                    ((unsigned long long)f2key(s_cost[r * NPRED + j]) << 32)
                    | (unsigned)j;
                best = min(best, key);
            }
        }
        #pragma unroll
        for (int off = 16; off > 0; off >>= 1)
            best = min(best, __shfl_xor_sync(0xffffffffu, best, off));
        if (lane == 0) s_rowkey[r] = best;
    }
    __syncthreads();

    // ---- greedy tight assignment + dual init (tid 0, serial over 32 rows) ----
    if (tid == 0) {
        int nf = 0;
        s_u[0] = 0.0f;
        for (int r = 0; r < MTGT; r++) {
            unsigned long long key = s_rowkey[r];
            int   jmin = (int)(key & 0xFFFFFFFFULL);
            float vmin = key2f((unsigned)(key >> 32));
            s_u[r + 1] = vmin;                    // u[i] = exact row min, v = 0
            if (s_p[jmin + 1] == 0) s_p[jmin + 1] = r + 1;   // tight edge, free col
            else                    s_freelist[nf++] = r + 1;
        }
        s_nfree = nf;
    }
    __syncthreads();

    // ---- JV augmentation for conflicted rows only (fp32, 1 barrier/iter,
    //      REDUX.min warp argmin, delta==0 fast path) ----
    const int  jcol   = tid + 1;
    const bool active = (tid < NPRED);
    float v = 0.0f;                        // v[jcol] in register (greedy leaves v=0)
    const int nfree = s_nfree;

    for (int fi = 0; fi < nfree; fi++) {
        const int i = s_freelist[fi];
        float mv    = FLT_MAX;
        bool  used  = false;
        if (tid == 0) s_p[0] = i;
        int j0  = 0;
        int par = 0;
        __syncthreads();   // phase start: s_p[0] + previous augment visible

        while (true) {
            // -- compute: scan own column against current row i0 --
            const int   i0   = s_p[j0];
            const float u_i0 = s_u[i0];

            unsigned vkey = 0xFFFFFFFFu;
            if (active && !used) {
                float cur = s_cost[(i0 - 1) * NPRED + tid] - u_i0 - v;
                if (cur < mv) { mv = cur; s_way[jcol] = j0; }
                vkey = f2key(mv);
            }
            // single-instruction warp min (value), then lowest-index tie-break
            unsigned vmin = __reduce_min_sync(0xffffffffu, vkey);
            unsigned jc   = (vkey == vmin) ? (unsigned)jcol : 0xFFFFFFFFu;
            unsigned jmin = __reduce_min_sync(0xffffffffu, jc);
            if (lane == 0)
                s_wmin[par][wid] = ((unsigned long long)vmin << 32) | jmin;
            __syncthreads();   // the ONE barrier

            // -- select: tree min over the 10 warp minima --
            const unsigned long long* wm = s_wmin[par];
            unsigned long long m0 = min(wm[0], wm[1]);
            unsigned long long m1 = min(wm[2], wm[3]);
            unsigned long long m2 = min(wm[4], wm[5]);
            unsigned long long m3 = min(wm[6], wm[7]);
            unsigned long long m4 = min(wm[8], wm[9]);
            unsigned long long kk = min(min(min(m0, m1), min(m2, m3)), m4);
            const int   j1    = (int)(kk & 0xFFFFFFFFULL);
            const float delta = key2f((unsigned)(kk >> 32));  // == owner's mv, exact
            const int   pj1   = s_p[j1];

            // -- update (delta==0: only the used-marking matters) --
            if (delta != 0.0f) {
                if (tid == 0) s_u[s_p[0]] += delta;       // free row (virtual col 0)
                if (active) {
                    if (used) {
                        v -= delta;
                        s_u[s_p[jcol]] += delta;          // distinct rows, no conflict
                    } else {
                        mv -= delta;
                        if (jcol == j1) used = true;
                    }
                }
            } else {
                if (active && !used && jcol == j1) used = true;
            }

            par ^= 1;
            j0 = j1;
            if (pj1 == 0) break;
        }

        // augment (scalar); visibility covered by next phase-start barrier
        if (tid == 0) {
            int jj = j0;
            while (jj) {
                int jn = s_way[jj];
                s_p[jj] = s_p[jn];
                jj = jn;
            }
        }
    }
    __syncthreads();

    // ---- emit matches to smem ----
    if (active) {
        const int r = s_p[jcol];
        if (r > 0) s_match[r - 1] = jcol - 1;
    }
    __syncthreads();

    // ---- L1 + pair GIoU: one thread per target ----
    if (tid < MTGT) {
        const int idx = s_match[tid];
        const float4 bp = ((const float4*)pb)[f * NPRED + idx];
        const float4 tc = s_tc[tid];
        const float4 tb = s_tb4[tid];
        const float  ta = s_ta[tid];
        float l1 = fabsf(bp.x - tc.x) + fabsf(bp.y - tc.y)
                 + fabsf(bp.z - tc.z) + fabsf(bp.w - tc.w);
        float ax1 = bp.x - 0.5f * bp.z, ay1 = bp.y - 0.5f * bp.w;
        float ax2 = bp.x + 0.5f * bp.z, ay2 = bp.y + 0.5f * bp.w;
        float aarea = (ax2 - ax1) * (ay2 - ay1);
        float ltx = fmaxf(ax1, tb.x), lty = fmaxf(ay1, tb.y);
        float rbx = fminf(ax2, tb.z), rby = fminf(ay2, tb.w);
        float iw = fmaxf(rbx - ltx, 0.f), ih = fmaxf(rby - lty, 0.f);
        float inter = iw * ih;
        float uni = aarea + ta - inter;
        float iou = __fdividef(inter, uni);
        float LTx = fminf(ax1, tb.x), LTy = fminf(ay1, tb.y);
        float RBx = fmaxf(ax2, tb.z), RBy = fmaxf(ay2, tb.w);
        float ac = fmaxf(RBx - LTx, 0.f) * fmaxf(RBy - LTy, 0.f);
        float g = iou - __fdividef(ac - uni, ac);
        atomicAdd(&s_acc[0], (double)l1);
        atomicAdd(&s_acc[1], (double)g);
    }

    // ---- ID cross-entropy: each warp handles ~3-4 rows of K=512 (float4 loads) ----
    double id_part = 0.0;
    for (int t = wid; t < MTGT; t += NWARPS) {
        const int idx = s_match[t];
        const float* row = il + (size_t)(f * NPRED + idx) * KID;
        const float4* row4 = (const float4*)row;
        float4 xv[4];
        #pragma unroll
        for (int q = 0; q < 4; q++) xv[q] = row4[lane + 32 * q];
        float mx = -FLT_MAX;
        #pragma unroll
        for (int q = 0; q < 4; q++) {
            mx = fmaxf(mx, fmaxf(fmaxf(xv[q].x, xv[q].y), fmaxf(xv[q].z, xv[q].w)));
        }
        #pragma unroll
        for (int off = 16; off > 0; off >>= 1)
            mx = fmaxf(mx, __shfl_xor_sync(0xffffffffu, mx, off));
        float se = 0.f;
        #pragma unroll
        for (int q = 0; q < 4; q++) {
            se += __expf(xv[q].x - mx) + __expf(xv[q].y - mx)
                + __expf(xv[q].z - mx) + __expf(xv[q].w - mx);
        }
        #pragma unroll
        for (int off = 16; off > 0; off >>= 1)
            se += __shfl_xor_sync(0xffffffffu, se, off);
        if (lane == 0) {
            float lse = __logf(se) + mx;
            int tg = tids[f * MTGT + t];
            id_part += (double)(lse - row[tg]);
        }
    }
    if (lane == 0 && id_part != 0.0) atomicAdd(&s_acc[2], id_part);
    __syncthreads();

    // ---- publish partials; last block finalizes ----
    if (tid == 0) {
        g_part[f * 3 + 0] = s_acc[0];
        g_part[f * 3 + 1] = s_acc[1];
        g_part[f * 3 + 2] = s_acc[2];
        __threadfence();
        unsigned t = atomicAdd(&g_done, 1u);
        s_islast = (t == F_FRAMES - 1) ? 1 : 0;
    }
    __syncthreads();

    if (s_islast) {
        __threadfence();
        double a0 = 0.0, a1 = 0.0, a2 = 0.0;
        if (tid < F_FRAMES) {
            a0 = g_part[tid * 3 + 0];
            a1 = g_part[tid * 3 + 1];
            a2 = g_part[tid * 3 + 2];
        }
        #pragma unroll
        for (int off = 16; off > 0; off >>= 1) {
            a0 += __shfl_down_sync(0xffffffffu, a0, off);
            a1 += __shfl_down_sync(0xffffffffu, a1, off);
            a2 += __shfl_down_sync(0xffffffffu, a2, off);
        }
        __shared__ double s0[4], s1[4], s2[4];
        if (lane == 0 && wid < 4) { s0[wid] = a0; s1[wid] = a1; s2[wid] = a2; }
        __syncthreads();
        if (tid == 0) {
            double t0 = s0[0] + s0[1] + s0[2] + s0[3];
            double t1 = s1[0] + s1[1] + s1[2] + s1[3];
            double t2 = s2[0] + s2[1] + s2[2] + s2[3];
            const double FM = (double)(F_FRAMES * MTGT);
            double l1   = t0 / (FM * 4.0);
            double giou = 1.0 - t1 / FM;
            double idl  = t2 / FM;
            double loss = 5.0 * l1 + 2.0 * giou + 1.0 * idl;
            out[0] = (float)loss;
            out[1] = 0.0f;
            out[2] = (float)l1;
            out[3] = (float)giou;
            out[4] = (float)idl;
            __threadfence();
            g_done = 0;      // self-reset for next graph replay
        }
    }
}

extern "C" void kernel_launch(void* const* d_in, const int* in_sizes, int n_in,
                              void* d_out, int out_size) {
    const float* pred_logits   = (const float*)d_in[0];  // [8,16,300,2]
    const float* pred_boxes    = (const float*)d_in[1];  // [8,16,300,4]
    const float* id_logits     = (const float*)d_in[2];  // [8,16,300,512]
    const int*   target_labels = (const int*)  d_in[3];  // [128,32]
    const float* target_boxes  = (const float*)d_in[4];  // [128,32,4]
    const int*   target_ids    = (const int*)  d_in[5];  // [128,32]
    float* out = (float*)d_out;

    motip_kernel<<<F_FRAMES, HTHREADS>>>(pred_logits, pred_boxes, id_logits,
                                         target_labels, target_boxes, target_ids,
                                         out);
}